// round 15
// baseline (speedup 1.0000x reference)
#include <cuda_runtime.h>
#include <cuda_bf16.h>
#include <cstdint>
#include <math.h>

typedef __nv_bfloat16 bf16;
#define ALG __align__(128)

// ---------- scratch ----------
__device__ ALG bf16 g_a1h[400u*42*42*64];
__device__ ALG bf16 g_a1l[400u*42*42*64];
__device__ ALG bf16 g_a2h[400u*21*21*64];
__device__ ALG bf16 g_a2l[400u*21*21*64];
__device__ ALG bf16 g_a3h[400u*10*10*128];
__device__ ALG bf16 g_a3l[400u*10*10*128];
__device__ ALG float g_f4[400u*512*25];
__device__ float g_fa[4u*5*512];
__device__ ALG bf16 g_w1q[64*64];
__device__ ALG bf16 g_w2h[9*64*64];   __device__ ALG bf16 g_w2l[9*64*64];
__device__ ALG bf16 g_w3h[9*128*64];  __device__ ALG bf16 g_w3l[9*128*64];
__device__ ALG bf16 g_w4h[9*2*512*64];__device__ ALG bf16 g_w4l[9*2*512*64];

// ---------- helpers ----------
__device__ __forceinline__ uint32_t smem_u32(const void* p) {
    uint32_t a;
    asm("{ .reg .u64 t; cvta.to.shared.u64 t, %1; cvt.u32.u64 %0, t; }" : "=r"(a) : "l"(p));
    return a;
}
__device__ __forceinline__ void ldsm_x4(uint32_t* r, uint32_t a) {
    asm volatile("ldmatrix.sync.aligned.m8n8.x4.shared.b16 {%0,%1,%2,%3}, [%4];"
        : "=r"(r[0]), "=r"(r[1]), "=r"(r[2]), "=r"(r[3]) : "r"(a));
}
__device__ __forceinline__ void ldsm_x2(uint32_t* r, uint32_t a) {
    asm volatile("ldmatrix.sync.aligned.m8n8.x2.shared.b16 {%0,%1}, [%2];"
        : "=r"(r[0]), "=r"(r[1]) : "r"(a));
}
__device__ __forceinline__ void mma16816(float4& d, const uint32_t* a, const uint32_t* b) {
    asm volatile("mma.sync.aligned.m16n8k16.row.col.f32.bf16.bf16.f32 "
        "{%0,%1,%2,%3},{%4,%5,%6,%7},{%8,%9},{%0,%1,%2,%3};"
        : "+f"(d.x), "+f"(d.y), "+f"(d.z), "+f"(d.w)
        : "r"(a[0]), "r"(a[1]), "r"(a[2]), "r"(a[3]), "r"(b[0]), "r"(b[1]));
}
__device__ __forceinline__ void cpa16(uint32_t dst, const void* src, int sz) {
    asm volatile("cp.async.cg.shared.global [%0], [%1], 16, %2;"
                 :: "r"(dst), "l"(src), "r"(sz) : "memory");
}
__device__ __forceinline__ void cpa4(uint32_t dst, const void* src, int sz) {
    asm volatile("cp.async.ca.shared.global [%0], [%1], 4, %2;"
                 :: "r"(dst), "l"(src), "r"(sz) : "memory");
}
#define CPA_COMMIT() asm volatile("cp.async.commit_group;" ::: "memory")
#define CPA_WAIT0()  asm volatile("cp.async.wait_group 0;" ::: "memory")

// ---------- fused weight repack (one launch) ----------
__global__ void repack_all_kernel(const float* __restrict__ w1, const float* __restrict__ w2,
                                  const float* __restrict__ w3, const float* __restrict__ w4,
                                  bf16* __restrict__ w1q,
                                  bf16* __restrict__ w2h, bf16* __restrict__ w2l,
                                  bf16* __restrict__ w3h, bf16* __restrict__ w3l,
                                  bf16* __restrict__ w4h, bf16* __restrict__ w4l)
{
    const int N1 = 64*32, N2 = 9*64*64, N3 = 9*128*64, N4 = 9*2*512*64;
    const int total = N1 + N2 + N3 + N4;
    for (int idx = blockIdx.x*blockDim.x + threadIdx.x; idx < total;
         idx += gridDim.x*blockDim.x) {
        if (idx < N1) {
            int co = idx >> 5, j = idx & 31;
            float v = (j < 27) ? w1[co*27 + j] : 0.f;
            bf16 h = __float2bfloat16(v);
            w1q[co*64 + j]      = h;
            w1q[co*64 + 32 + j] = __float2bfloat16(v - __bfloat162float(h));
            continue;
        }
        int i; const float* w; bf16 *oh, *ol; int cin, cout;
        if (idx < N1 + N2)        { i = idx - N1;       w = w2; oh = w2h; ol = w2l; cin = 64;  cout = 64; }
        else if (idx < N1+N2+N3)  { i = idx - N1 - N2;  w = w3; oh = w3h; ol = w3l; cin = 64;  cout = 128; }
        else                      { i = idx - N1-N2-N3; w = w4; oh = w4h; ol = w4l; cin = 128; cout = 512; }
        int nc = cin / 64;
        int cil = i & 63, t = i >> 6;
        int co = t % cout; t /= cout;
        int cic = t % nc;  t /= nc;
        int k = t;
        float v = w[((size_t)co*cin + cic*64 + cil)*9 + k];
        bf16 h = __float2bfloat16(v);
        oh[i] = h; ol[i] = __float2bfloat16(v - __bfloat162float(h));
    }
}

// ---------- L1 as HMMA: im2col K=32 (27 used), pixels-on-M, N=64 ----------
__global__ void __launch_bounds__(256)
conv1_mma(const float* __restrict__ inA, const float* __restrict__ inB, int nsplit,
          const bf16* __restrict__ wq, const float* __restrict__ bias,
          bf16* __restrict__ outh, bf16* __restrict__ outl)
{
    constexpr int HPO = 42, WPO = 42, NPX = 42*42;
    constexpr uint32_t oBand = 0, oA = 6400, oB = 6400 + 16384;
    extern __shared__ char dsm[];
    char* smp = (char*)(((uintptr_t)dsm + 1023) & ~(uintptr_t)1023);
    const uint32_t sb = smem_u32(smp);
    float* sband = reinterpret_cast<float*>(smp + oBand);
    const int tid = threadIdx.x, wid = tid >> 5, lane = tid & 31;
    const int img = blockIdx.z, ppb = blockIdx.x * 32;
    const int r0 = ppb / WPO;
    const int ystart = 2*r0 - 1;

    const float* im = (img < nsplit) ? inA + (size_t)img*3*84*84
                                     : inB + (size_t)(img - nsplit)*3*84*84;

    for (int g = tid; g < 3*6*88; g += 256) {
        int ci = g / 528, rem = g - ci*528;
        int row = rem / 88, col = rem - row*88;
        int y = ystart + row, x = col - 1;
        bool ok = (y >= 0 && y < 84 && x >= 0 && x < 84);
        cpa4(sb + oBand + (uint32_t)g*4, im + (ok ? ((size_t)ci*7056 + y*84 + x) : 0), ok ? 4 : 0);
    }
    for (int g = tid; g < 64*8; g += 256) {
        int r = g >> 3, seg = g & 7;
        cpa16(sb + oB + r*128 + ((seg ^ (r & 7)) << 4), wq + r*64 + seg*8, 16);
    }
    CPA_COMMIT();
    CPA_WAIT0();
    __syncthreads();

    {
        const int p = tid >> 1, half = tid & 1;
        const int pp = ppb + (p >> 2), q = p & 3;
        const bool rv = pp < NPX;
        int by0 = 0, bx0 = 0;
        if (rv) {
            int cy = 2*(pp/WPO) + (q >> 1);
            int cx = 2*(pp%WPO) + (q & 1);
            by0 = cy - 1 - ystart;
            bx0 = cx;
        }
        unsigned short hv[16], lv[16];
        #pragma unroll
        for (int j = 0; j < 16; j++) { hv[j] = 0; lv[j] = 0; }
        #pragma unroll
        for (int ci = 0; ci < 3; ci++)
            #pragma unroll
            for (int tap = 0; tap < 9; tap++) {
                int j = ci*9 + tap;
                if ((j >> 4) != half) continue;
                float v = rv ? sband[(ci*6 + by0 + tap/3)*88 + bx0 + tap%3] : 0.f;
                bf16 h = __float2bfloat16(v);
                hv[j & 15] = __bfloat16_as_ushort(h);
                lv[j & 15] = __bfloat16_as_ushort(__float2bfloat16(v - __bfloat162float(h)));
            }
        uint32_t hw[8], lw[8];
        #pragma unroll
        for (int c = 0; c < 8; c++) {
            hw[c] = hv[2*c] | ((uint32_t)hv[2*c+1] << 16);
            lw[c] = lv[2*c] | ((uint32_t)lv[2*c+1] << 16);
        }
        const uint32_t rb = sb + oA + p*128;
        const int px = p & 7;
        asm volatile("st.shared.v4.b32 [%0], {%1,%2,%3,%4};" :: "r"(rb + (((half*2 + 0) ^ px) << 4)),
                     "r"(hw[0]), "r"(hw[1]), "r"(hw[2]), "r"(hw[3]));
        asm volatile("st.shared.v4.b32 [%0], {%1,%2,%3,%4};" :: "r"(rb + (((half*2 + 1) ^ px) << 4)),
                     "r"(hw[4]), "r"(hw[5]), "r"(hw[6]), "r"(hw[7]));
        asm volatile("st.shared.v4.b32 [%0], {%1,%2,%3,%4};" :: "r"(rb + (((4 + half*2 + 0) ^ px) << 4)),
                     "r"(lw[0]), "r"(lw[1]), "r"(lw[2]), "r"(lw[3]));
        asm volatile("st.shared.v4.b32 [%0], {%1,%2,%3,%4};" :: "r"(rb + (((4 + half*2 + 1) ^ px) << 4)),
                     "r"(lw[4]), "r"(lw[5]), "r"(lw[6]), "r"(lw[7]));
    }
    __syncthreads();

    float4 acc[8];
    #pragma unroll
    for (int i = 0; i < 8; i++) acc[i] = make_float4(0,0,0,0);
    const int aRow = wid*16 + (lane & 15);
    const int aXor = aRow & 7, aHalf = lane >> 4;
    const int bRow8 = (lane >> 4)*8 + (lane & 7);
    const int bHalf = (lane >> 3) & 1, bx = lane & 7;
    #pragma unroll
    for (int ks = 0; ks < 2; ks++) {
        uint32_t ah[4], al[4];
        const uint32_t ab = sb + oA + aRow*128;
        ldsm_x4(ah, ab + (((2*ks + aHalf) ^ aXor) << 4));
        ldsm_x4(al, ab + (((4 + 2*ks + aHalf) ^ aXor) << 4));
        #pragma unroll
        for (int p = 0; p < 4; p++) {
            const uint32_t rbase = sb + oB + (p*16 + bRow8)*128;
            uint32_t bh[4], bl[4];
            ldsm_x4(bh, rbase + (((2*ks + bHalf) ^ bx) << 4));
            ldsm_x4(bl, rbase + (((4 + 2*ks + bHalf) ^ bx) << 4));
            mma16816(acc[2*p],   ah, bh);     mma16816(acc[2*p],   al, bh);
            mma16816(acc[2*p],   ah, bl);
            mma16816(acc[2*p+1], ah, bh + 2); mma16816(acc[2*p+1], al, bh + 2);
            mma16816(acc[2*p+1], ah, bl + 2);
        }
    }

    __syncthreads();
    float* so = reinterpret_cast<float*>(smp);
    {
        const int row = wid*16 + (lane >> 2);
        const int col = 2*(lane & 3);
        #pragma unroll
        for (int nb = 0; nb < 8; nb++) {
            so[row*64 + nb*8 + col]       = acc[nb].x;
            so[row*64 + nb*8 + col + 1]   = acc[nb].y;
            so[(row+8)*64 + nb*8 + col]   = acc[nb].z;
            so[(row+8)*64 + nb*8 + col+1] = acc[nb].w;
        }
    }
    __syncthreads();
    for (int g = tid; g < 32*8; g += 256) {
        int pp_l = g >> 3, cg = g & 7;
        int pp = ppb + pp_l;
        if (pp >= NPX) continue;
        int co0 = cg*8;
        float v[8];
        #pragma unroll
        for (int j = 0; j < 8; j++) v[j] = -1e30f;
        #pragma unroll
        for (int q = 0; q < 4; q++) {
            const float* rp = &so[(4*pp_l + q)*64 + co0];
            #pragma unroll
            for (int j = 0; j < 8; j++) v[j] = fmaxf(v[j], rp[j]);
        }
        unsigned short hh[8], ll[8];
        #pragma unroll
        for (int j = 0; j < 8; j++) {
            float t = fmaxf(v[j] + bias[co0 + j], 0.f);
            bf16 h = __float2bfloat16(t);
            hh[j] = __bfloat16_as_ushort(h);
            ll[j] = __bfloat16_as_ushort(__float2bfloat16(t - __bfloat162float(h)));
        }
        size_t base = (((size_t)img*HPO + pp/WPO)*WPO + pp%WPO)*64 + co0;
        *reinterpret_cast<uint4*>(outh + base) =
            make_uint4(hh[0]|((uint32_t)hh[1]<<16), hh[2]|((uint32_t)hh[3]<<16),
                       hh[4]|((uint32_t)hh[5]<<16), hh[6]|((uint32_t)hh[7]<<16));
        *reinterpret_cast<uint4*>(outl + base) =
            make_uint4(ll[0]|((uint32_t)ll[1]<<16), ll[2]|((uint32_t)ll[3]<<16),
                       ll[4]|((uint32_t)ll[5]<<16), ll[6]|((uint32_t)ll[7]<<16));
    }
}

// ---------- HMMA conv, pixels-on-M (L2, L3): NT=256, MP=32, single-buffered B ----------
template<int COUT, int HIN, int WIN, int HPO, int WPO, int NROWS, int PW>
__global__ void __launch_bounds__(256, 2)
conv_mma_px(const bf16* __restrict__ inh, const bf16* __restrict__ inl,
            const bf16* __restrict__ wh,  const bf16* __restrict__ wl,
            const float* __restrict__ bias,
            bf16* __restrict__ outh, bf16* __restrict__ outl)
{
    constexpr int NT = 256, MP = 32;
    constexpr int NB = COUT/8;
    constexpr int NPAIR = NB/2;
    constexpr int BANDPX = NROWS*PW;
    constexpr uint32_t BH = BANDPX*128;
    constexpr uint32_t CB = COUT*128;
    constexpr uint32_t oB = 2*BH;

    extern __shared__ char dsm[];
    char* smp = (char*)(((uintptr_t)dsm + 1023) & ~(uintptr_t)1023);
    const uint32_t sb = smem_u32(smp);
    const int tid = threadIdx.x, wid = tid >> 5, lane = tid & 31;
    const int img = blockIdx.z, ppb = blockIdx.x * MP;
    const int r0 = ppb / WPO;
    const int ystart = 2*r0 - 1;

    const bf16* ih = inh + (size_t)img * HIN * WIN * 64;
    const bf16* il = inl + (size_t)img * HIN * WIN * 64;

    for (int g = tid; g < BANDPX*8; g += NT) {
        int p = g >> 3, seg = g & 7;
        int row = p / PW, col = p % PW;
        int gy = ystart + row, gx = col - 1;
        bool ok = (gy >= 0 && gy < HIN && gx >= 0 && gx < WIN);
        size_t s = ok ? (((size_t)gy*WIN + gx)*64 + seg*8) : 0;
        uint32_t d = p*128 + ((seg ^ (p & 7)) << 4);
        cpa16(sb + d,      ih + s, ok ? 16 : 0);
        cpa16(sb + BH + d, il + s, ok ? 16 : 0);
    }
    for (int g = tid; g < COUT*8; g += NT) {
        int r = g >> 3, seg = g & 7;
        uint32_t d = sb + oB + r*128 + ((seg ^ (r & 7)) << 4);
        size_t s = (size_t)r*64 + seg*8;
        cpa16(d,      wh + s, 16);
        cpa16(d + CB, wl + s, 16);
    }
    CPA_COMMIT();

    float4 acc[NB];
    #pragma unroll
    for (int i = 0; i < NB; i++) acc[i] = make_float4(0,0,0,0);

    const int aRow = wid*16 + (lane & 15);
    const int appd = aRow >> 2, aq = aRow & 3;
    const int ay = 2*((ppb + appd)/WPO) + (aq >> 1);
    const int ax = 2*((ppb + appd)%WPO) + (aq & 1);
    const int p00 = (ay - 2*r0)*PW + ax;
    const int aHalf = lane >> 4;
    const int bRow8 = (lane >> 4)*8 + (lane & 7);
    const int bHalf = (lane >> 3) & 1, bx = lane & 7;

    for (int k = 0; k < 9; k++) {
        if (k > 0) {
            __syncthreads();
            for (int g = tid; g < COUT*8; g += NT) {
                int r = g >> 3, seg = g & 7;
                uint32_t d = sb + oB + r*128 + ((seg ^ (r & 7)) << 4);
                size_t s = ((size_t)k*COUT + r)*64 + seg*8;
                cpa16(d,      wh + s, 16);
                cpa16(d + CB, wl + s, 16);
            }
            CPA_COMMIT();
        }
        CPA_WAIT0();
        __syncthreads();
        const int pA = p00 + (k/3)*PW + (k%3);
        const uint32_t aBaseH = sb + pA*128;
        const uint32_t aBaseL = sb + BH + pA*128;
        const int aXor = pA & 7;
        #pragma unroll
        for (int ks = 0; ks < 4; ks++) {
            uint32_t ah[4], al[4];
            const uint32_t ao = (uint32_t)(((2*ks + aHalf) ^ aXor) << 4);
            ldsm_x4(ah, aBaseH + ao);
            ldsm_x4(al, aBaseL + ao);
            #pragma unroll
            for (int p = 0; p < NPAIR; p++) {
                const uint32_t rbase = sb + oB + (p*16 + bRow8)*128 + (((2*ks + bHalf) ^ bx) << 4);
                uint32_t bh[4], bl[4];
                ldsm_x4(bh, rbase);
                ldsm_x4(bl, rbase + CB);
                mma16816(acc[2*p],   ah, bh);     mma16816(acc[2*p],   al, bh);
                mma16816(acc[2*p],   ah, bl);
                mma16816(acc[2*p+1], ah, bh + 2); mma16816(acc[2*p+1], al, bh + 2);
                mma16816(acc[2*p+1], ah, bl + 2);
            }
        }
    }

    __syncthreads();
    float* so = reinterpret_cast<float*>(smp);
    {
        const int row = wid*16 + (lane >> 2);
        const int col = 2*(lane & 3);
        #pragma unroll
        for (int nb = 0; nb < NB; nb++) {
            so[row*COUT + nb*8 + col]       = acc[nb].x;
            so[row*COUT + nb*8 + col + 1]   = acc[nb].y;
            so[(row+8)*COUT + nb*8 + col]   = acc[nb].z;
            so[(row+8)*COUT + nb*8 + col+1] = acc[nb].w;
        }
    }
    __syncthreads();
    for (int g = tid; g < MP*NB; g += NT) {
        int pp_l = g / NB, cg = g % NB;
        int pp = ppb + pp_l;
        if (pp >= HPO*WPO) continue;
        int co0 = cg*8;
        float v[8];
        #pragma unroll
        for (int j = 0; j < 8; j++) v[j] = -1e30f;
        #pragma unroll
        for (int q = 0; q < 4; q++) {
            const float* rp = &so[(4*pp_l + q)*COUT + co0];
            #pragma unroll
            for (int j = 0; j < 8; j++) v[j] = fmaxf(v[j], rp[j]);
        }
        unsigned short hh[8], ll[8];
        #pragma unroll
        for (int j = 0; j < 8; j++) {
            float t = fmaxf(v[j] + bias[co0 + j], 0.f);
            bf16 h = __float2bfloat16(t);
            hh[j] = __bfloat16_as_ushort(h);
            ll[j] = __bfloat16_as_ushort(__float2bfloat16(t - __bfloat162float(h)));
        }
        size_t base = (((size_t)img*HPO + pp/WPO)*WPO + pp%WPO)*COUT + co0;
        *reinterpret_cast<uint4*>(outh + base) =
            make_uint4(hh[0]|((uint32_t)hh[1]<<16), hh[2]|((uint32_t)hh[3]<<16),
                       hh[4]|((uint32_t)hh[5]<<16), hh[6]|((uint32_t)hh[7]<<16));
        *reinterpret_cast<uint4*>(outl + base) =
            make_uint4(ll[0]|((uint32_t)ll[1]<<16), ll[2]|((uint32_t)ll[3]<<16),
                       ll[4]|((uint32_t)ll[5]<<16), ll[6]|((uint32_t)ll[7]<<16));
    }
}

// ---------- HMMA conv, co-on-M (L4): NT=256, 12x12 band, single-buffered A ----------
__global__ void __launch_bounds__(256, 2)
conv_mma_co(const bf16* __restrict__ inh, const bf16* __restrict__ inl,
            const bf16* __restrict__ wh,  const bf16* __restrict__ wl,
            const float* __restrict__ bias, float* __restrict__ outf)
{
    constexpr int NT = 256;
    constexpr uint32_t PXB = 144*256;
    constexpr uint32_t oPxL = PXB, oA = 2*PXB;

    extern __shared__ char dsm[];
    char* smp = (char*)(((uintptr_t)dsm + 1023) & ~(uintptr_t)1023);
    const uint32_t sb = smem_u32(smp);
    const int tid = threadIdx.x, wid = tid >> 5, lane = tid & 31;
    const int img = blockIdx.z, cob = blockIdx.y * 128;

    const bf16* ih = inh + (size_t)img * 100 * 128;
    const bf16* il = inl + (size_t)img * 100 * 128;

    for (int g = tid; g < 144*16; g += NT) {
        int p = g >> 4, seg = g & 15;
        int row = p / 12, col = p % 12;
        int gy = row - 1, gx = col - 1;
        bool ok = (gy >= 0 && gy < 10 && gx >= 0 && gx < 10);
        size_t s = ok ? ((size_t)(gy*10 + gx)*128 + seg*8) : 0;
        uint32_t d = p*256 + ((seg ^ (p & 7)) << 4);
        cpa16(sb + d,        ih + s, ok ? 16 : 0);
        cpa16(sb + oPxL + d, il + s, ok ? 16 : 0);
    }
    for (int g = tid; g < 1024; g += NT) {
        int m = g >> 3, seg = g & 7;
        size_t s = ((size_t)cob + m)*64 + seg*8;
        uint32_t d = sb + oA + m*128 + ((seg ^ (m & 7)) << 4);
        cpa16(d,         wh + s, 16);
        cpa16(d + 16384, wl + s, 16);
    }
    CPA_COMMIT();

    float4 acc[13];
    #pragma unroll
    for (int i = 0; i < 13; i++) acc[i] = make_float4(0,0,0,0);

    const int aRow = wid*16 + (lane & 15);
    const int aXor = aRow & 7, aHalf = lane >> 4;
    const int bHalf = (lane >> 3) & 1;
    int pb0[7];
    #pragma unroll
    for (int p = 0; p < 7; p++) {
        int n = (p < 6) ? (p*16 + (lane >> 4)*8 + (lane & 7)) : (96 + (lane & 7));
        int pp = n >> 2, q = n & 3;
        if (pp < 25) {
            int y = 2*(pp/5) + (q >> 1);
            int x = 2*(pp%5) + (q & 1);
            pb0[p] = (y + 1)*12 + (x + 1);
        } else pb0[p] = 20;
    }

    for (int it = 0; it < 18; it++) {
        if (it > 0) {
            __syncthreads();
            int kn = it >> 1, cn = it & 1;
            for (int g = tid; g < 1024; g += NT) {
                int m = g >> 3, seg = g & 7;
                size_t s = ((size_t)(kn*2 + cn)*512 + cob + m)*64 + seg*8;
                uint32_t d = sb + oA + m*128 + ((seg ^ (m & 7)) << 4);
                cpa16(d,         wh + s, 16);
                cpa16(d + 16384, wl + s, 16);
            }
            CPA_COMMIT();
        }
        CPA_WAIT0();
        __syncthreads();
        const int k = it >> 1, cic = it & 1;
        const int dtap = (k/3 - 1)*12 + (k%3 - 1);
        const uint32_t aBase = sb + oA + aRow*128;
        #pragma unroll
        for (int ks = 0; ks < 4; ks++) {
            uint32_t ah[4], al[4];
            const uint32_t ao = (uint32_t)(((2*ks + aHalf) ^ aXor) << 4);
            ldsm_x4(ah, aBase + ao);
            ldsm_x4(al, aBase + 16384 + ao);
            #pragma unroll
            for (int p = 0; p < 6; p++) {
                const int pb = pb0[p] + dtap;
                const uint32_t bo = sb + pb*256 + ((((cic<<3) + 2*ks + bHalf) ^ (pb & 7)) << 4);
                uint32_t bh[4], bl[4];
                ldsm_x4(bh, bo);
                ldsm_x4(bl, bo + oPxL);
                mma16816(acc[2*p],   ah, bh);     mma16816(acc[2*p],   al, bh);
                mma16816(acc[2*p],   ah, bl);
                mma16816(acc[2*p+1], ah, bh + 2); mma16816(acc[2*p+1], al, bh + 2);
                mma16816(acc[2*p+1], ah, bl + 2);
            }
            {
                const int pb = pb0[6] + dtap;
                const uint32_t bo = sb + pb*256 + ((((cic<<3) + 2*ks + bHalf) ^ (pb & 7)) << 4);
                uint32_t bh[2], bl[2];
                ldsm_x2(bh, bo);
                ldsm_x2(bl, bo + oPxL);
                mma16816(acc[12], ah, bh);
                mma16816(acc[12], al, bh);
                mma16816(acc[12], ah, bl);
            }
        }
    }

    __syncthreads();
    float* so = reinterpret_cast<float*>(smp);
    {
        const int row = wid*16 + (lane >> 2);
        const int col = 2*(lane & 3);
        #pragma unroll
        for (int nb = 0; nb < 13; nb++) {
            so[row*104 + nb*8 + col]       = acc[nb].x;
            so[row*104 + nb*8 + col + 1]   = acc[nb].y;
            so[(row+8)*104 + nb*8 + col]   = acc[nb].z;
            so[(row+8)*104 + nb*8 + col+1] = acc[nb].w;
        }
    }
    __syncthreads();
    for (int g = tid; g < 3200; g += NT) {
        int co_l = g / 25, pp = g % 25;
        float4 q4 = *reinterpret_cast<float4*>(&so[co_l*104 + 4*pp]);
        float v = fmaxf(fmaxf(q4.x, q4.y), fmaxf(q4.z, q4.w));
        v = fmaxf(v + bias[cob + co_l], 0.f);
        outf[((size_t)img*512 + cob + co_l)*25 + pp] = v;
    }
}

// ---------- prototypes / head / scores ----------
__global__ void proto_kernel(const float* __restrict__ ytr) {
    const int bk = blockIdx.x, b = bk/5, k = bk - b*5, c = threadIdx.x;
    float ssum = 0.f, ysum = 0.f;
    for (int n = 0; n < 25; n++) {
        float y = ytr[(b*25 + n)*5 + k];
        ysum += y;
        if (y != 0.f) {
            const float* fp = &g_f4[((size_t)(b*25 + n)*512 + c)*25];
            float sp = 0.f;
            #pragma unroll
            for (int p = 0; p < 25; p++) sp += fp[p];
            ssum = fmaf(y, sp, ssum);
        }
    }
    float val = ssum / (ysum * 25.f);
    __shared__ float red[512];
    red[c] = val*val; __syncthreads();
    for (int o = 256; o > 0; o >>= 1) { if (c < o) red[c] += red[c+o]; __syncthreads(); }
    g_fa[(size_t)bk*512 + c] = val / fmaxf(sqrtf(red[0]), 1e-12f);
}
__global__ void predict_kernel(const float* __restrict__ wc, const float* __restrict__ bc,
                               float* __restrict__ out) {
    const int q = blockIdx.x, c = threadIdx.x;
    const float* fp = &g_f4[((size_t)(100 + q)*512 + c)*25];
    float s = 0.f;
    #pragma unroll
    for (int p = 0; p < 25; p++) s += fp[p];
    s /= 25.f;
    __shared__ float red[512], sf[512];
    red[c] = s*s; __syncthreads();
    for (int o = 256; o > 0; o >>= 1) { if (c < o) red[c] += red[c+o]; __syncthreads(); }
    sf[c] = s / fmaxf(sqrtf(red[0]), 1e-12f);
    __syncthreads();
    if (c < 64) {
        float a = bc[c];
        const float* wr = &wc[(size_t)c*512];
        #pragma unroll 8
        for (int d = 0; d < 512; d++) a = fmaf(sf[d], wr[d], a);
        out[(size_t)q*64 + c] = a;
    }
}
__global__ void score_kernel(float* __restrict__ out) {
    constexpr int CH = 128;
    __shared__ float sf[CH*25], sfa[5*129], snrm[25];
    const int q = blockIdx.x, b = q/75, tid = threadIdx.x;
    const float* fbase = &g_f4[(size_t)(100 + q)*512*25];
    float acc = 0.f;
    const int di = tid/25, dp = tid%25, pn = tid - 125;
    for (int cb = 0; cb < 4; cb++) {
        __syncthreads();
        for (int i = tid; i < CH*25; i += 256) sf[i] = fbase[cb*CH*25 + i];
        for (int i = tid; i < 5*CH; i += 256) {
            int ii = i/CH, cc = i - ii*CH;
            sfa[ii*129 + cc] = g_fa[((size_t)(b*5 + ii))*512 + cb*CH + cc];
        }
        __syncthreads();
        if (tid < 125) {
            #pragma unroll 4
            for (int c = 0; c < CH; c++) acc = fmaf(sf[c*25 + dp], sfa[di*129 + c], acc);
        } else if (tid < 150) {
            #pragma unroll 4
            for (int c = 0; c < CH; c++) { float v = sf[c*25 + pn]; acc = fmaf(v, v, acc); }
        }
    }
    if (tid >= 125 && tid < 150) snrm[pn] = fmaxf(sqrtf(acc), 1e-12f);
    __syncthreads();
    if (tid < 125) out[(size_t)q*125 + tid] = acc / snrm[dp];
}

// ---------- launch ----------
extern "C" void kernel_launch(void* const* d_in, const int* in_sizes, int n_in,
                              void* d_out, int out_size)
{
    const float* xtr = (const float*)d_in[0];
    const float* xte = (const float*)d_in[1];
    const float* ytr = (const float*)d_in[2];
    const float* w1 = (const float*)d_in[4];  const float* b1 = (const float*)d_in[5];
    const float* w2 = (const float*)d_in[6];  const float* b2 = (const float*)d_in[7];
    const float* w3 = (const float*)d_in[8];  const float* b3 = (const float*)d_in[9];
    const float* w4 = (const float*)d_in[10]; const float* b4 = (const float*)d_in[11];
    const float* wc = (const float*)d_in[12]; const float* bc = (const float*)d_in[13];
    float* out = (float*)d_out;

    float *f4;
    bf16 *a1h,*a1l,*a2h,*a2l,*a3h,*a3l,*w1q,*w2h,*w2l,*w3h,*w3l,*w4h,*w4l;
    cudaGetSymbolAddress((void**)&f4, g_f4);
    cudaGetSymbolAddress((void**)&w1q, g_w1q);
    cudaGetSymbolAddress((void**)&a1h, g_a1h); cudaGetSymbolAddress((void**)&a1l, g_a1l);
    cudaGetSymbolAddress((void**)&a2h, g_a2h); cudaGetSymbolAddress((void**)&a2l, g_a2l);
    cudaGetSymbolAddress((void**)&a3h, g_a3h); cudaGetSymbolAddress((void**)&a3l, g_a3l);
    cudaGetSymbolAddress((void**)&w2h, g_w2h); cudaGetSymbolAddress((void**)&w2l, g_w2l);
    cudaGetSymbolAddress((void**)&w3h, g_w3h); cudaGetSymbolAddress((void**)&w3l, g_w3l);
    cudaGetSymbolAddress((void**)&w4h, g_w4h); cudaGetSymbolAddress((void**)&w4l, g_w4l);

    repack_all_kernel<<<1372, 512>>>(w1, w2, w3, w4, w1q, w2h, w2l, w3h, w3l, w4h, w4l);

    {   // L1 HMMA
        int sm = 33792;
        cudaFuncSetAttribute(conv1_mma, cudaFuncAttributeMaxDynamicSharedMemorySize, sm);
        conv1_mma<<<dim3(56, 1, 400), 256, sm>>>(xtr, xte, 100, w1q, b1, a1h, a1l);
    }
    {   // L2: 64->64, MP=32, band 8x44, single-buf B  (2 blocks/SM)
        auto kfn = conv_mma_px<64, 42, 42, 21, 21, 8, 44>;
        int sm = 1024 + 2*(8*44*128) + 2*(64*128);
        cudaFuncSetAttribute(kfn, cudaFuncAttributeMaxDynamicSharedMemorySize, sm);
        kfn<<<dim3(14, 1, 400), 256, sm>>>(a1h, a1l, w2h, w2l, b2, a2h, a2l);
    }
    {   // L3: 64->128, MP=32, band 10x28, single-buf B (2 blocks/SM)
        auto kfn = conv_mma_px<128, 21, 21, 10, 10, 10, 28>;
        int sm = 1024 + 2*(10*28*128) + 2*(128*128);
        cudaFuncSetAttribute(kfn, cudaFuncAttributeMaxDynamicSharedMemorySize, sm);
        kfn<<<dim3(4, 1, 400), 256, sm>>>(a2h, a2l, w3h, w3l, b3, a3h, a3l);
    }
    {   // L4: 128->512, 12x12 band, single-buf A (2 blocks/SM)
        int sm = 1024 + 2*(144*256) + 32768;
        cudaFuncSetAttribute(conv_mma_co, cudaFuncAttributeMaxDynamicSharedMemorySize, sm);
        conv_mma_co<<<dim3(1, 4, 400), 256, sm>>>(a3h, a3l, w4h, w4l, b4, f4);
    }

    proto_kernel<<<20, 512>>>(ytr);
    predict_kernel<<<300, 512>>>(wc, bc, out);
    score_kernel<<<300, 256>>>(out + 300*64);
}

// round 16
// speedup vs baseline: 1.2977x; 1.2977x over previous
#include <cuda_runtime.h>
#include <cuda_bf16.h>
#include <cstdint>
#include <math.h>

typedef __nv_bfloat16 bf16;
#define ALG __align__(128)

// ---------- scratch ----------
__device__ ALG bf16 g_a1h[400u*42*42*64];
__device__ ALG bf16 g_a1l[400u*42*42*64];
__device__ ALG bf16 g_a2h[400u*21*21*64];
__device__ ALG bf16 g_a2l[400u*21*21*64];
__device__ ALG bf16 g_a3h[400u*10*10*128];
__device__ ALG bf16 g_a3l[400u*10*10*128];
__device__ ALG float g_f4[400u*512*25];
__device__ float g_fa[4u*5*512];
__device__ ALG bf16 g_w1q[64*64];
__device__ ALG bf16 g_w2h[9*64*64];   __device__ ALG bf16 g_w2l[9*64*64];
__device__ ALG bf16 g_w3h[9*128*64];  __device__ ALG bf16 g_w3l[9*128*64];
__device__ ALG bf16 g_w4h[9*2*512*64];__device__ ALG bf16 g_w4l[9*2*512*64];

// ---------- helpers ----------
__device__ __forceinline__ uint32_t smem_u32(const void* p) {
    uint32_t a;
    asm("{ .reg .u64 t; cvta.to.shared.u64 t, %1; cvt.u32.u64 %0, t; }" : "=r"(a) : "l"(p));
    return a;
}
__device__ __forceinline__ void ldsm_x4(uint32_t* r, uint32_t a) {
    asm volatile("ldmatrix.sync.aligned.m8n8.x4.shared.b16 {%0,%1,%2,%3}, [%4];"
        : "=r"(r[0]), "=r"(r[1]), "=r"(r[2]), "=r"(r[3]) : "r"(a));
}
__device__ __forceinline__ void ldsm_x2(uint32_t* r, uint32_t a) {
    asm volatile("ldmatrix.sync.aligned.m8n8.x2.shared.b16 {%0,%1}, [%2];"
        : "=r"(r[0]), "=r"(r[1]) : "r"(a));
}
__device__ __forceinline__ void mma16816(float4& d, const uint32_t* a, const uint32_t* b) {
    asm volatile("mma.sync.aligned.m16n8k16.row.col.f32.bf16.bf16.f32 "
        "{%0,%1,%2,%3},{%4,%5,%6,%7},{%8,%9},{%0,%1,%2,%3};"
        : "+f"(d.x), "+f"(d.y), "+f"(d.z), "+f"(d.w)
        : "r"(a[0]), "r"(a[1]), "r"(a[2]), "r"(a[3]), "r"(b[0]), "r"(b[1]));
}
__device__ __forceinline__ void cpa16(uint32_t dst, const void* src, int sz) {
    asm volatile("cp.async.cg.shared.global [%0], [%1], 16, %2;"
                 :: "r"(dst), "l"(src), "r"(sz) : "memory");
}
__device__ __forceinline__ void cpa4(uint32_t dst, const void* src, int sz) {
    asm volatile("cp.async.ca.shared.global [%0], [%1], 4, %2;"
                 :: "r"(dst), "l"(src), "r"(sz) : "memory");
}
#define CPA_COMMIT() asm volatile("cp.async.commit_group;" ::: "memory")
#define CPA_WAIT0()  asm volatile("cp.async.wait_group 0;" ::: "memory")

// ---------- weight repacks ----------
__global__ void repack_w1_kernel(const float* __restrict__ w, bf16* __restrict__ o) {
    int i = blockIdx.x*blockDim.x + threadIdx.x;
    if (i >= 64*32) return;
    int co = i >> 5, j = i & 31;
    float v = (j < 27) ? w[co*27 + j] : 0.f;
    bf16 h = __float2bfloat16(v);
    o[co*64 + j]      = h;
    o[co*64 + 32 + j] = __float2bfloat16(v - __bfloat162float(h));
}
__global__ void repack_bf16_kernel(const float* __restrict__ w, bf16* __restrict__ oh,
                                   bf16* __restrict__ ol, int cin, int cout) {
    int nc = cin / 64, total = 9 * nc * cout * 64;
    for (int i = blockIdx.x*blockDim.x + threadIdx.x; i < total; i += gridDim.x*blockDim.x) {
        int cil = i & 63, t = i >> 6;
        int co = t % cout; t /= cout;
        int cic = t % nc;  t /= nc;
        int k = t;
        float v = w[((size_t)co*cin + cic*64 + cil)*9 + k];
        bf16 h = __float2bfloat16(v);
        oh[i] = h; ol[i] = __float2bfloat16(v - __bfloat162float(h));
    }
}

// ---------- L1 as HMMA: im2col K=32 (27 used), pixels-on-M, N=64 ----------
__global__ void __launch_bounds__(256)
conv1_mma(const float* __restrict__ inA, const float* __restrict__ inB, int nsplit,
          const bf16* __restrict__ wq, const float* __restrict__ bias,
          bf16* __restrict__ outh, bf16* __restrict__ outl)
{
    constexpr int HPO = 42, WPO = 42, NPX = 42*42;
    constexpr uint32_t oBand = 0, oA = 6400, oB = 6400 + 16384;
    extern __shared__ char dsm[];
    char* smp = (char*)(((uintptr_t)dsm + 1023) & ~(uintptr_t)1023);
    const uint32_t sb = smem_u32(smp);
    float* sband = reinterpret_cast<float*>(smp + oBand);
    const int tid = threadIdx.x, wid = tid >> 5, lane = tid & 31;
    const int img = blockIdx.z, ppb = blockIdx.x * 32;
    const int r0 = ppb / WPO;
    const int ystart = 2*r0 - 1;

    const float* im = (img < nsplit) ? inA + (size_t)img*3*84*84
                                     : inB + (size_t)(img - nsplit)*3*84*84;

    for (int g = tid; g < 3*6*88; g += 256) {
        int ci = g / 528, rem = g - ci*528;
        int row = rem / 88, col = rem - row*88;
        int y = ystart + row, x = col - 1;
        bool ok = (y >= 0 && y < 84 && x >= 0 && x < 84);
        cpa4(sb + oBand + (uint32_t)g*4, im + (ok ? ((size_t)ci*7056 + y*84 + x) : 0), ok ? 4 : 0);
    }
    for (int g = tid; g < 64*8; g += 256) {
        int r = g >> 3, seg = g & 7;
        cpa16(sb + oB + r*128 + ((seg ^ (r & 7)) << 4), wq + r*64 + seg*8, 16);
    }
    CPA_COMMIT();
    CPA_WAIT0();
    __syncthreads();

    {
        const int p = tid >> 1, half = tid & 1;
        const int pp = ppb + (p >> 2), q = p & 3;
        const bool rv = pp < NPX;
        int by0 = 0, bx0 = 0;
        if (rv) {
            int cy = 2*(pp/WPO) + (q >> 1);
            int cx = 2*(pp%WPO) + (q & 1);
            by0 = cy - 1 - ystart;
            bx0 = cx;
        }
        unsigned short hv[16], lv[16];
        #pragma unroll
        for (int j = 0; j < 16; j++) { hv[j] = 0; lv[j] = 0; }
        #pragma unroll
        for (int ci = 0; ci < 3; ci++)
            #pragma unroll
            for (int tap = 0; tap < 9; tap++) {
                int j = ci*9 + tap;
                if ((j >> 4) != half) continue;
                float v = rv ? sband[(ci*6 + by0 + tap/3)*88 + bx0 + tap%3] : 0.f;
                bf16 h = __float2bfloat16(v);
                hv[j & 15] = __bfloat16_as_ushort(h);
                lv[j & 15] = __bfloat16_as_ushort(__float2bfloat16(v - __bfloat162float(h)));
            }
        uint32_t hw[8], lw[8];
        #pragma unroll
        for (int c = 0; c < 8; c++) {
            hw[c] = hv[2*c] | ((uint32_t)hv[2*c+1] << 16);
            lw[c] = lv[2*c] | ((uint32_t)lv[2*c+1] << 16);
        }
        const uint32_t rb = sb + oA + p*128;
        const int px = p & 7;
        asm volatile("st.shared.v4.b32 [%0], {%1,%2,%3,%4};" :: "r"(rb + (((half*2 + 0) ^ px) << 4)),
                     "r"(hw[0]), "r"(hw[1]), "r"(hw[2]), "r"(hw[3]));
        asm volatile("st.shared.v4.b32 [%0], {%1,%2,%3,%4};" :: "r"(rb + (((half*2 + 1) ^ px) << 4)),
                     "r"(hw[4]), "r"(hw[5]), "r"(hw[6]), "r"(hw[7]));
        asm volatile("st.shared.v4.b32 [%0], {%1,%2,%3,%4};" :: "r"(rb + (((4 + half*2 + 0) ^ px) << 4)),
                     "r"(lw[0]), "r"(lw[1]), "r"(lw[2]), "r"(lw[3]));
        asm volatile("st.shared.v4.b32 [%0], {%1,%2,%3,%4};" :: "r"(rb + (((4 + half*2 + 1) ^ px) << 4)),
                     "r"(lw[4]), "r"(lw[5]), "r"(lw[6]), "r"(lw[7]));
    }
    __syncthreads();

    float4 acc[8];
    #pragma unroll
    for (int i = 0; i < 8; i++) acc[i] = make_float4(0,0,0,0);
    const int aRow = wid*16 + (lane & 15);
    const int aXor = aRow & 7, aHalf = lane >> 4;
    const int bRow8 = (lane >> 4)*8 + (lane & 7);
    const int bHalf = (lane >> 3) & 1, bx = lane & 7;
    #pragma unroll
    for (int ks = 0; ks < 2; ks++) {
        uint32_t ah[4], al[4];
        const uint32_t ab = sb + oA + aRow*128;
        ldsm_x4(ah, ab + (((2*ks + aHalf) ^ aXor) << 4));
        ldsm_x4(al, ab + (((4 + 2*ks + aHalf) ^ aXor) << 4));
        #pragma unroll
        for (int p = 0; p < 4; p++) {
            const uint32_t rbase = sb + oB + (p*16 + bRow8)*128;
            uint32_t bh[4], bl[4];
            ldsm_x4(bh, rbase + (((2*ks + bHalf) ^ bx) << 4));
            ldsm_x4(bl, rbase + (((4 + 2*ks + bHalf) ^ bx) << 4));
            mma16816(acc[2*p],   ah, bh);     mma16816(acc[2*p],   al, bh);
            mma16816(acc[2*p],   ah, bl);
            mma16816(acc[2*p+1], ah, bh + 2); mma16816(acc[2*p+1], al, bh + 2);
            mma16816(acc[2*p+1], ah, bl + 2);
        }
    }

    __syncthreads();
    float* so = reinterpret_cast<float*>(smp);
    {
        const int row = wid*16 + (lane >> 2);
        const int col = 2*(lane & 3);
        #pragma unroll
        for (int nb = 0; nb < 8; nb++) {
            so[row*64 + nb*8 + col]       = acc[nb].x;
            so[row*64 + nb*8 + col + 1]   = acc[nb].y;
            so[(row+8)*64 + nb*8 + col]   = acc[nb].z;
            so[(row+8)*64 + nb*8 + col+1] = acc[nb].w;
        }
    }
    __syncthreads();
    for (int g = tid; g < 32*8; g += 256) {
        int pp_l = g >> 3, cg = g & 7;
        int pp = ppb + pp_l;
        if (pp >= NPX) continue;
        int co0 = cg*8;
        float v[8];
        #pragma unroll
        for (int j = 0; j < 8; j++) v[j] = -1e30f;
        #pragma unroll
        for (int q = 0; q < 4; q++) {
            const float* rp = &so[(4*pp_l + q)*64 + co0];
            #pragma unroll
            for (int j = 0; j < 8; j++) v[j] = fmaxf(v[j], rp[j]);
        }
        unsigned short hh[8], ll[8];
        #pragma unroll
        for (int j = 0; j < 8; j++) {
            float t = fmaxf(v[j] + bias[co0 + j], 0.f);
            bf16 h = __float2bfloat16(t);
            hh[j] = __bfloat16_as_ushort(h);
            ll[j] = __bfloat16_as_ushort(__float2bfloat16(t - __bfloat162float(h)));
        }
        size_t base = (((size_t)img*HPO + pp/WPO)*WPO + pp%WPO)*64 + co0;
        *reinterpret_cast<uint4*>(outh + base) =
            make_uint4(hh[0]|((uint32_t)hh[1]<<16), hh[2]|((uint32_t)hh[3]<<16),
                       hh[4]|((uint32_t)hh[5]<<16), hh[6]|((uint32_t)hh[7]<<16));
        *reinterpret_cast<uint4*>(outl + base) =
            make_uint4(ll[0]|((uint32_t)ll[1]<<16), ll[2]|((uint32_t)ll[3]<<16),
                       ll[4]|((uint32_t)ll[5]<<16), ll[6]|((uint32_t)ll[7]<<16));
    }
}

// ---------- HMMA conv, pixels-on-M (L2, L3): NT=256, MP=32, single-buffered B ----------
template<int COUT, int HIN, int WIN, int HPO, int WPO, int NROWS, int PW>
__global__ void __launch_bounds__(256, 2)
conv_mma_px(const bf16* __restrict__ inh, const bf16* __restrict__ inl,
            const bf16* __restrict__ wh,  const bf16* __restrict__ wl,
            const float* __restrict__ bias,
            bf16* __restrict__ outh, bf16* __restrict__ outl)
{
    constexpr int NT = 256, MP = 32;
    constexpr int NB = COUT/8;
    constexpr int NPAIR = NB/2;
    constexpr int BANDPX = NROWS*PW;
    constexpr uint32_t BH = BANDPX*128;
    constexpr uint32_t CB = COUT*128;
    constexpr uint32_t oB = 2*BH;

    extern __shared__ char dsm[];
    char* smp = (char*)(((uintptr_t)dsm + 1023) & ~(uintptr_t)1023);
    const uint32_t sb = smem_u32(smp);
    const int tid = threadIdx.x, wid = tid >> 5, lane = tid & 31;
    const int img = blockIdx.z, ppb = blockIdx.x * MP;
    const int r0 = ppb / WPO;
    const int ystart = 2*r0 - 1;

    const bf16* ih = inh + (size_t)img * HIN * WIN * 64;
    const bf16* il = inl + (size_t)img * HIN * WIN * 64;

    for (int g = tid; g < BANDPX*8; g += NT) {
        int p = g >> 3, seg = g & 7;
        int row = p / PW, col = p % PW;
        int gy = ystart + row, gx = col - 1;
        bool ok = (gy >= 0 && gy < HIN && gx >= 0 && gx < WIN);
        size_t s = ok ? (((size_t)gy*WIN + gx)*64 + seg*8) : 0;
        uint32_t d = p*128 + ((seg ^ (p & 7)) << 4);
        cpa16(sb + d,      ih + s, ok ? 16 : 0);
        cpa16(sb + BH + d, il + s, ok ? 16 : 0);
    }
    for (int g = tid; g < COUT*8; g += NT) {
        int r = g >> 3, seg = g & 7;
        uint32_t d = sb + oB + r*128 + ((seg ^ (r & 7)) << 4);
        size_t s = (size_t)r*64 + seg*8;
        cpa16(d,      wh + s, 16);
        cpa16(d + CB, wl + s, 16);
    }
    CPA_COMMIT();

    float4 acc[NB];
    #pragma unroll
    for (int i = 0; i < NB; i++) acc[i] = make_float4(0,0,0,0);

    const int aRow = wid*16 + (lane & 15);
    const int appd = aRow >> 2, aq = aRow & 3;
    const int ay = 2*((ppb + appd)/WPO) + (aq >> 1);
    const int ax = 2*((ppb + appd)%WPO) + (aq & 1);
    const int p00 = (ay - 2*r0)*PW + ax;
    const int aHalf = lane >> 4;
    const int bRow8 = (lane >> 4)*8 + (lane & 7);
    const int bHalf = (lane >> 3) & 1, bx = lane & 7;

    for (int k = 0; k < 9; k++) {
        if (k > 0) {
            __syncthreads();
            for (int g = tid; g < COUT*8; g += NT) {
                int r = g >> 3, seg = g & 7;
                uint32_t d = sb + oB + r*128 + ((seg ^ (r & 7)) << 4);
                size_t s = ((size_t)k*COUT + r)*64 + seg*8;
                cpa16(d,      wh + s, 16);
                cpa16(d + CB, wl + s, 16);
            }
            CPA_COMMIT();
        }
        CPA_WAIT0();
        __syncthreads();
        const int pA = p00 + (k/3)*PW + (k%3);
        const uint32_t aBaseH = sb + pA*128;
        const uint32_t aBaseL = sb + BH + pA*128;
        const int aXor = pA & 7;
        #pragma unroll
        for (int ks = 0; ks < 4; ks++) {
            uint32_t ah[4], al[4];
            const uint32_t ao = (uint32_t)(((2*ks + aHalf) ^ aXor) << 4);
            ldsm_x4(ah, aBaseH + ao);
            ldsm_x4(al, aBaseL + ao);
            #pragma unroll
            for (int p = 0; p < NPAIR; p++) {
                const uint32_t rbase = sb + oB + (p*16 + bRow8)*128 + (((2*ks + bHalf) ^ bx) << 4);
                uint32_t bh[4], bl[4];
                ldsm_x4(bh, rbase);
                ldsm_x4(bl, rbase + CB);
                mma16816(acc[2*p],   ah, bh);     mma16816(acc[2*p],   al, bh);
                mma16816(acc[2*p],   ah, bl);
                mma16816(acc[2*p+1], ah, bh + 2); mma16816(acc[2*p+1], al, bh + 2);
                mma16816(acc[2*p+1], ah, bl + 2);
            }
        }
    }

    __syncthreads();
    float* so = reinterpret_cast<float*>(smp);
    {
        const int row = wid*16 + (lane >> 2);
        const int col = 2*(lane & 3);
        #pragma unroll
        for (int nb = 0; nb < NB; nb++) {
            so[row*COUT + nb*8 + col]       = acc[nb].x;
            so[row*COUT + nb*8 + col + 1]   = acc[nb].y;
            so[(row+8)*COUT + nb*8 + col]   = acc[nb].z;
            so[(row+8)*COUT + nb*8 + col+1] = acc[nb].w;
        }
    }
    __syncthreads();
    for (int g = tid; g < MP*NB; g += NT) {
        int pp_l = g / NB, cg = g % NB;
        int pp = ppb + pp_l;
        if (pp >= HPO*WPO) continue;
        int co0 = cg*8;
        float v[8];
        #pragma unroll
        for (int j = 0; j < 8; j++) v[j] = -1e30f;
        #pragma unroll
        for (int q = 0; q < 4; q++) {
            const float* rp = &so[(4*pp_l + q)*COUT + co0];
            #pragma unroll
            for (int j = 0; j < 8; j++) v[j] = fmaxf(v[j], rp[j]);
        }
        unsigned short hh[8], ll[8];
        #pragma unroll
        for (int j = 0; j < 8; j++) {
            float t = fmaxf(v[j] + bias[co0 + j], 0.f);
            bf16 h = __float2bfloat16(t);
            hh[j] = __bfloat16_as_ushort(h);
            ll[j] = __bfloat16_as_ushort(__float2bfloat16(t - __bfloat162float(h)));
        }
        size_t base = (((size_t)img*HPO + pp/WPO)*WPO + pp%WPO)*COUT + co0;
        *reinterpret_cast<uint4*>(outh + base) =
            make_uint4(hh[0]|((uint32_t)hh[1]<<16), hh[2]|((uint32_t)hh[3]<<16),
                       hh[4]|((uint32_t)hh[5]<<16), hh[6]|((uint32_t)hh[7]<<16));
        *reinterpret_cast<uint4*>(outl + base) =
            make_uint4(ll[0]|((uint32_t)ll[1]<<16), ll[2]|((uint32_t)ll[3]<<16),
                       ll[4]|((uint32_t)ll[5]<<16), ll[6]|((uint32_t)ll[7]<<16));
    }
}

// ---------- HMMA conv, co-on-M (L4): NT=256, 12x12 band, single-buffered A ----------
__global__ void __launch_bounds__(256, 2)
conv_mma_co(const bf16* __restrict__ inh, const bf16* __restrict__ inl,
            const bf16* __restrict__ wh,  const bf16* __restrict__ wl,
            const float* __restrict__ bias, float* __restrict__ outf)
{
    constexpr int NT = 256;
    constexpr uint32_t PXB = 144*256;
    constexpr uint32_t oPxL = PXB, oA = 2*PXB;

    extern __shared__ char dsm[];
    char* smp = (char*)(((uintptr_t)dsm + 1023) & ~(uintptr_t)1023);
    const uint32_t sb = smem_u32(smp);
    const int tid = threadIdx.x, wid = tid >> 5, lane = tid & 31;
    const int img = blockIdx.z, cob = blockIdx.y * 128;

    const bf16* ih = inh + (size_t)img * 100 * 128;
    const bf16* il = inl + (size_t)img * 100 * 128;

    for (int g = tid; g < 144*16; g += NT) {
        int p = g >> 4, seg = g & 15;
        int row = p / 12, col = p % 12;
        int gy = row - 1, gx = col - 1;
        bool ok = (gy >= 0 && gy < 10 && gx >= 0 && gx < 10);
        size_t s = ok ? ((size_t)(gy*10 + gx)*128 + seg*8) : 0;
        uint32_t d = p*256 + ((seg ^ (p & 7)) << 4);
        cpa16(sb + d,        ih + s, ok ? 16 : 0);
        cpa16(sb + oPxL + d, il + s, ok ? 16 : 0);
    }
    for (int g = tid; g < 1024; g += NT) {
        int m = g >> 3, seg = g & 7;
        size_t s = ((size_t)cob + m)*64 + seg*8;
        uint32_t d = sb + oA + m*128 + ((seg ^ (m & 7)) << 4);
        cpa16(d,         wh + s, 16);
        cpa16(d + 16384, wl + s, 16);
    }
    CPA_COMMIT();

    float4 acc[13];
    #pragma unroll
    for (int i = 0; i < 13; i++) acc[i] = make_float4(0,0,0,0);

    const int aRow = wid*16 + (lane & 15);
    const int aXor = aRow & 7, aHalf = lane >> 4;
    const int bHalf = (lane >> 3) & 1;
    int pb0[7];
    #pragma unroll
    for (int p = 0; p < 7; p++) {
        int n = (p < 6) ? (p*16 + (lane >> 4)*8 + (lane & 7)) : (96 + (lane & 7));
        int pp = n >> 2, q = n & 3;
        if (pp < 25) {
            int y = 2*(pp/5) + (q >> 1);
            int x = 2*(pp%5) + (q & 1);
            pb0[p] = (y + 1)*12 + (x + 1);
        } else pb0[p] = 20;
    }

    for (int it = 0; it < 18; it++) {
        if (it > 0) {
            __syncthreads();
            int kn = it >> 1, cn = it & 1;
            for (int g = tid; g < 1024; g += NT) {
                int m = g >> 3, seg = g & 7;
                size_t s = ((size_t)(kn*2 + cn)*512 + cob + m)*64 + seg*8;
                uint32_t d = sb + oA + m*128 + ((seg ^ (m & 7)) << 4);
                cpa16(d,         wh + s, 16);
                cpa16(d + 16384, wl + s, 16);
            }
            CPA_COMMIT();
        }
        CPA_WAIT0();
        __syncthreads();
        const int k = it >> 1, cic = it & 1;
        const int dtap = (k/3 - 1)*12 + (k%3 - 1);
        const uint32_t aBase = sb + oA + aRow*128;
        #pragma unroll
        for (int ks = 0; ks < 4; ks++) {
            uint32_t ah[4], al[4];
            const uint32_t ao = (uint32_t)(((2*ks + aHalf) ^ aXor) << 4);
            ldsm_x4(ah, aBase + ao);
            ldsm_x4(al, aBase + 16384 + ao);
            #pragma unroll
            for (int p = 0; p < 6; p++) {
                const int pb = pb0[p] + dtap;
                const uint32_t bo = sb + pb*256 + ((((cic<<3) + 2*ks + bHalf) ^ (pb & 7)) << 4);
                uint32_t bh[4], bl[4];
                ldsm_x4(bh, bo);
                ldsm_x4(bl, bo + oPxL);
                mma16816(acc[2*p],   ah, bh);     mma16816(acc[2*p],   al, bh);
                mma16816(acc[2*p],   ah, bl);
                mma16816(acc[2*p+1], ah, bh + 2); mma16816(acc[2*p+1], al, bh + 2);
                mma16816(acc[2*p+1], ah, bl + 2);
            }
            {
                const int pb = pb0[6] + dtap;
                const uint32_t bo = sb + pb*256 + ((((cic<<3) + 2*ks + bHalf) ^ (pb & 7)) << 4);
                uint32_t bh[2], bl[2];
                ldsm_x2(bh, bo);
                ldsm_x2(bl, bo + oPxL);
                mma16816(acc[12], ah, bh);
                mma16816(acc[12], al, bh);
                mma16816(acc[12], ah, bl);
            }
        }
    }

    __syncthreads();
    float* so = reinterpret_cast<float*>(smp);
    {
        const int row = wid*16 + (lane >> 2);
        const int col = 2*(lane & 3);
        #pragma unroll
        for (int nb = 0; nb < 13; nb++) {
            so[row*104 + nb*8 + col]       = acc[nb].x;
            so[row*104 + nb*8 + col + 1]   = acc[nb].y;
            so[(row+8)*104 + nb*8 + col]   = acc[nb].z;
            so[(row+8)*104 + nb*8 + col+1] = acc[nb].w;
        }
    }
    __syncthreads();
    for (int g = tid; g < 3200; g += NT) {
        int co_l = g / 25, pp = g % 25;
        float4 q4 = *reinterpret_cast<float4*>(&so[co_l*104 + 4*pp]);
        float v = fmaxf(fmaxf(q4.x, q4.y), fmaxf(q4.z, q4.w));
        v = fmaxf(v + bias[cob + co_l], 0.f);
        outf[((size_t)img*512 + cob + co_l)*25 + pp] = v;
    }
}

// ---------- prototypes / head / scores ----------
__global__ void proto_kernel(const float* __restrict__ ytr) {
    const int bk = blockIdx.x, b = bk/5, k = bk - b*5, c = threadIdx.x;
    float ssum = 0.f, ysum = 0.f;
    for (int n = 0; n < 25; n++) {
        float y = ytr[(b*25 + n)*5 + k];
        ysum += y;
        if (y != 0.f) {
            const float* fp = &g_f4[((size_t)(b*25 + n)*512 + c)*25];
            float sp = 0.f;
            #pragma unroll
            for (int p = 0; p < 25; p++) sp += fp[p];
            ssum = fmaf(y, sp, ssum);
        }
    }
    float val = ssum / (ysum * 25.f);
    __shared__ float red[512];
    red[c] = val*val; __syncthreads();
    for (int o = 256; o > 0; o >>= 1) { if (c < o) red[c] += red[c+o]; __syncthreads(); }
    g_fa[(size_t)bk*512 + c] = val / fmaxf(sqrtf(red[0]), 1e-12f);
}
__global__ void predict_kernel(const float* __restrict__ wc, const float* __restrict__ bc,
                               float* __restrict__ out) {
    const int q = blockIdx.x, c = threadIdx.x;
    const float* fp = &g_f4[((size_t)(100 + q)*512 + c)*25];
    float s = 0.f;
    #pragma unroll
    for (int p = 0; p < 25; p++) s += fp[p];
    s /= 25.f;
    __shared__ float red[512], sf[512];
    red[c] = s*s; __syncthreads();
    for (int o = 256; o > 0; o >>= 1) { if (c < o) red[c] += red[c+o]; __syncthreads(); }
    sf[c] = s / fmaxf(sqrtf(red[0]), 1e-12f);
    __syncthreads();
    if (c < 64) {
        float a = bc[c];
        const float* wr = &wc[(size_t)c*512];
        #pragma unroll 8
        for (int d = 0; d < 512; d++) a = fmaf(sf[d], wr[d], a);
        out[(size_t)q*64 + c] = a;
    }
}
__global__ void score_kernel(float* __restrict__ out) {
    constexpr int CH = 128;
    __shared__ float sf[CH*25], sfa[5*129], snrm[25];
    const int q = blockIdx.x, b = q/75, tid = threadIdx.x;
    const float* fbase = &g_f4[(size_t)(100 + q)*512*25];
    float acc = 0.f;
    const int di = tid/25, dp = tid%25, pn = tid - 125;
    for (int cb = 0; cb < 4; cb++) {
        __syncthreads();
        for (int i = tid; i < CH*25; i += 256) sf[i] = fbase[cb*CH*25 + i];
        for (int i = tid; i < 5*CH; i += 256) {
            int ii = i/CH, cc = i - ii*CH;
            sfa[ii*129 + cc] = g_fa[((size_t)(b*5 + ii))*512 + cb*CH + cc];
        }
        __syncthreads();
        if (tid < 125) {
            #pragma unroll 4
            for (int c = 0; c < CH; c++) acc = fmaf(sf[c*25 + dp], sfa[di*129 + c], acc);
        } else if (tid < 150) {
            #pragma unroll 4
            for (int c = 0; c < CH; c++) { float v = sf[c*25 + pn]; acc = fmaf(v, v, acc); }
        }
    }
    if (tid >= 125 && tid < 150) snrm[pn] = fmaxf(sqrtf(acc), 1e-12f);
    __syncthreads();
    if (tid < 125) out[(size_t)q*125 + tid] = acc / snrm[dp];
}

// ---------- launch ----------
extern "C" void kernel_launch(void* const* d_in, const int* in_sizes, int n_in,
                              void* d_out, int out_size)
{
    const float* xtr = (const float*)d_in[0];
    const float* xte = (const float*)d_in[1];
    const float* ytr = (const float*)d_in[2];
    const float* w1 = (const float*)d_in[4];  const float* b1 = (const float*)d_in[5];
    const float* w2 = (const float*)d_in[6];  const float* b2 = (const float*)d_in[7];
    const float* w3 = (const float*)d_in[8];  const float* b3 = (const float*)d_in[9];
    const float* w4 = (const float*)d_in[10]; const float* b4 = (const float*)d_in[11];
    const float* wc = (const float*)d_in[12]; const float* bc = (const float*)d_in[13];
    float* out = (float*)d_out;

    float *f4;
    bf16 *a1h,*a1l,*a2h,*a2l,*a3h,*a3l,*w1q,*w2h,*w2l,*w3h,*w3l,*w4h,*w4l;
    cudaGetSymbolAddress((void**)&f4, g_f4);
    cudaGetSymbolAddress((void**)&w1q, g_w1q);
    cudaGetSymbolAddress((void**)&a1h, g_a1h); cudaGetSymbolAddress((void**)&a1l, g_a1l);
    cudaGetSymbolAddress((void**)&a2h, g_a2h); cudaGetSymbolAddress((void**)&a2l, g_a2l);
    cudaGetSymbolAddress((void**)&a3h, g_a3h); cudaGetSymbolAddress((void**)&a3l, g_a3l);
    cudaGetSymbolAddress((void**)&w2h, g_w2h); cudaGetSymbolAddress((void**)&w2l, g_w2l);
    cudaGetSymbolAddress((void**)&w3h, g_w3h); cudaGetSymbolAddress((void**)&w3l, g_w3l);
    cudaGetSymbolAddress((void**)&w4h, g_w4h); cudaGetSymbolAddress((void**)&w4l, g_w4l);

    repack_w1_kernel<<<8, 256>>>(w1, w1q);
    repack_bf16_kernel<<<144, 256>>>(w2, w2h, w2l, 64, 64);
    repack_bf16_kernel<<<288, 256>>>(w3, w3h, w3l, 64, 128);
    repack_bf16_kernel<<<2304, 256>>>(w4, w4h, w4l, 128, 512);

    {   // L1 HMMA
        int sm = 33792;
        cudaFuncSetAttribute(conv1_mma, cudaFuncAttributeMaxDynamicSharedMemorySize, sm);
        conv1_mma<<<dim3(56, 1, 400), 256, sm>>>(xtr, xte, 100, w1q, b1, a1h, a1l);
    }
    {   // L2: 64->64, MP=32, band 8x44, single-buf B  (2 blocks/SM)
        auto kfn = conv_mma_px<64, 42, 42, 21, 21, 8, 44>;
        int sm = 1024 + 2*(8*44*128) + 2*(64*128);
        cudaFuncSetAttribute(kfn, cudaFuncAttributeMaxDynamicSharedMemorySize, sm);
        kfn<<<dim3(14, 1, 400), 256, sm>>>(a1h, a1l, w2h, w2l, b2, a2h, a2l);
    }
    {   // L3: 64->128, MP=32, band 10x28, single-buf B (2 blocks/SM)
        auto kfn = conv_mma_px<128, 21, 21, 10, 10, 10, 28>;
        int sm = 1024 + 2*(10*28*128) + 2*(128*128);
        cudaFuncSetAttribute(kfn, cudaFuncAttributeMaxDynamicSharedMemorySize, sm);
        kfn<<<dim3(4, 1, 400), 256, sm>>>(a2h, a2l, w3h, w3l, b3, a3h, a3l);
    }
    {   // L4: 128->512, 12x12 band, single-buf A (2 blocks/SM)
        int sm = 1024 + 2*(144*256) + 32768;
        cudaFuncSetAttribute(conv_mma_co, cudaFuncAttributeMaxDynamicSharedMemorySize, sm);
        conv_mma_co<<<dim3(1, 4, 400), 256, sm>>>(a3h, a3l, w4h, w4l, b4, f4);
    }

    proto_kernel<<<20, 512>>>(ytr);
    predict_kernel<<<300, 512>>>(wc, bc, out);
    score_kernel<<<300, 256>>>(out + 300*64);
}

// round 17
// speedup vs baseline: 1.5686x; 1.2087x over previous
#include <cuda_runtime.h>
#include <cuda_fp16.h>
#include <cstdint>
#include <math.h>

typedef __half f16;
#define ALG __align__(128)

// ---------- scratch ----------
__device__ ALG f16 g_a1h[400u*42*42*64];
__device__ ALG f16 g_a1l[400u*42*42*64];
__device__ ALG f16 g_a2h[400u*21*21*64];
__device__ ALG f16 g_a2l[400u*21*21*64];
__device__ ALG f16 g_a3h[400u*10*10*128];
__device__ ALG f16 g_a3l[400u*10*10*128];
__device__ ALG float g_f4[400u*512*25];
__device__ float g_fa[4u*5*512];
__device__ ALG f16 g_w1q[64*64];        // [co][w 32 | zeros 32]
__device__ ALG f16 g_w2[9*64*64];
__device__ ALG f16 g_w3[9*128*64];
__device__ ALG f16 g_w4[9*2*512*64];

// ---------- helpers ----------
__device__ __forceinline__ uint32_t smem_u32(const void* p) {
    uint32_t a;
    asm("{ .reg .u64 t; cvta.to.shared.u64 t, %1; cvt.u32.u64 %0, t; }" : "=r"(a) : "l"(p));
    return a;
}
__device__ __forceinline__ void ldsm_x4(uint32_t* r, uint32_t a) {
    asm volatile("ldmatrix.sync.aligned.m8n8.x4.shared.b16 {%0,%1,%2,%3}, [%4];"
        : "=r"(r[0]), "=r"(r[1]), "=r"(r[2]), "=r"(r[3]) : "r"(a));
}
__device__ __forceinline__ void ldsm_x2(uint32_t* r, uint32_t a) {
    asm volatile("ldmatrix.sync.aligned.m8n8.x2.shared.b16 {%0,%1}, [%2];"
        : "=r"(r[0]), "=r"(r[1]) : "r"(a));
}
__device__ __forceinline__ void mma16816(float4& d, const uint32_t* a, const uint32_t* b) {
    asm volatile("mma.sync.aligned.m16n8k16.row.col.f32.f16.f16.f32 "
        "{%0,%1,%2,%3},{%4,%5,%6,%7},{%8,%9},{%0,%1,%2,%3};"
        : "+f"(d.x), "+f"(d.y), "+f"(d.z), "+f"(d.w)
        : "r"(a[0]), "r"(a[1]), "r"(a[2]), "r"(a[3]), "r"(b[0]), "r"(b[1]));
}
__device__ __forceinline__ void cpa16(uint32_t dst, const void* src, int sz) {
    asm volatile("cp.async.cg.shared.global [%0], [%1], 16, %2;"
                 :: "r"(dst), "l"(src), "r"(sz) : "memory");
}
__device__ __forceinline__ void cpa4(uint32_t dst, const void* src, int sz) {
    asm volatile("cp.async.ca.shared.global [%0], [%1], 4, %2;"
                 :: "r"(dst), "l"(src), "r"(sz) : "memory");
}
#define CPA_COMMIT() asm volatile("cp.async.commit_group;" ::: "memory")
#define CPA_WAIT0()  asm volatile("cp.async.wait_group 0;" ::: "memory")

// ---------- weight repacks ----------
__global__ void repack_w1_kernel(const float* __restrict__ w, f16* __restrict__ o) {
    int i = blockIdx.x*blockDim.x + threadIdx.x;
    if (i >= 64*32) return;
    int co = i >> 5, j = i & 31;
    float v = (j < 27) ? w[co*27 + j] : 0.f;
    o[co*64 + j]      = __float2half_rn(v);
    o[co*64 + 32 + j] = __float2half_rn(0.f);
}
__global__ void repack_f16_kernel(const float* __restrict__ w, f16* __restrict__ o,
                                  int cin, int cout) {
    int nc = cin / 64, total = 9 * nc * cout * 64;
    for (int i = blockIdx.x*blockDim.x + threadIdx.x; i < total; i += gridDim.x*blockDim.x) {
        int cil = i & 63, t = i >> 6;
        int co = t % cout; t /= cout;
        int cic = t % nc;  t /= nc;
        int k = t;
        o[i] = __float2half_rn(w[((size_t)co*cin + cic*64 + cil)*9 + k]);
    }
}

// ---------- L1 as HMMA: im2col K=32 (27 used), pixels-on-M, N=64 ----------
// A = image hi/lo fp16 (split side), B = weights single fp16. 2 passes.
__global__ void __launch_bounds__(256)
conv1_mma(const float* __restrict__ inA, const float* __restrict__ inB, int nsplit,
          const f16* __restrict__ wq, const float* __restrict__ bias,
          f16* __restrict__ outh, f16* __restrict__ outl)
{
    constexpr int HPO = 42, WPO = 42, NPX = 42*42;
    constexpr uint32_t oBand = 0, oA = 6400, oB = 6400 + 16384;
    extern __shared__ char dsm[];
    char* smp = (char*)(((uintptr_t)dsm + 1023) & ~(uintptr_t)1023);
    const uint32_t sb = smem_u32(smp);
    float* sband = reinterpret_cast<float*>(smp + oBand);
    const int tid = threadIdx.x, wid = tid >> 5, lane = tid & 31;
    const int img = blockIdx.z, ppb = blockIdx.x * 32;
    const int r0 = ppb / WPO;
    const int ystart = 2*r0 - 1;

    const float* im = (img < nsplit) ? inA + (size_t)img*3*84*84
                                     : inB + (size_t)(img - nsplit)*3*84*84;

    for (int g = tid; g < 3*6*88; g += 256) {
        int ci = g / 528, rem = g - ci*528;
        int row = rem / 88, col = rem - row*88;
        int y = ystart + row, x = col - 1;
        bool ok = (y >= 0 && y < 84 && x >= 0 && x < 84);
        cpa4(sb + oBand + (uint32_t)g*4, im + (ok ? ((size_t)ci*7056 + y*84 + x) : 0), ok ? 4 : 0);
    }
    for (int g = tid; g < 64*8; g += 256) {
        int r = g >> 3, seg = g & 7;
        cpa16(sb + oB + r*128 + ((seg ^ (r & 7)) << 4), wq + r*64 + seg*8, 16);
    }
    CPA_COMMIT();
    CPA_WAIT0();
    __syncthreads();

    // A tile: 128 px rows x [hi 32 | lo 32] fp16, swizzled
    {
        const int p = tid >> 1, half = tid & 1;
        const int pp = ppb + (p >> 2), q = p & 3;
        const bool rv = pp < NPX;
        int by0 = 0, bx0 = 0;
        if (rv) {
            int cy = 2*(pp/WPO) + (q >> 1);
            int cx = 2*(pp%WPO) + (q & 1);
            by0 = cy - 1 - ystart;
            bx0 = cx;
        }
        unsigned short hv[16], lv[16];
        #pragma unroll
        for (int j = 0; j < 16; j++) { hv[j] = 0; lv[j] = 0; }
        #pragma unroll
        for (int ci = 0; ci < 3; ci++)
            #pragma unroll
            for (int tap = 0; tap < 9; tap++) {
                int j = ci*9 + tap;
                if ((j >> 4) != half) continue;
                float v = rv ? sband[(ci*6 + by0 + tap/3)*88 + bx0 + tap%3] : 0.f;
                f16 h = __float2half_rn(v);
                hv[j & 15] = __half_as_ushort(h);
                lv[j & 15] = __half_as_ushort(__float2half_rn(v - __half2float(h)));
            }
        uint32_t hw[8], lw[8];
        #pragma unroll
        for (int c = 0; c < 8; c++) {
            hw[c] = hv[2*c] | ((uint32_t)hv[2*c+1] << 16);
            lw[c] = lv[2*c] | ((uint32_t)lv[2*c+1] << 16);
        }
        const uint32_t rb = sb + oA + p*128;
        const int px = p & 7;
        asm volatile("st.shared.v4.b32 [%0], {%1,%2,%3,%4};" :: "r"(rb + (((half*2 + 0) ^ px) << 4)),
                     "r"(hw[0]), "r"(hw[1]), "r"(hw[2]), "r"(hw[3]));
        asm volatile("st.shared.v4.b32 [%0], {%1,%2,%3,%4};" :: "r"(rb + (((half*2 + 1) ^ px) << 4)),
                     "r"(hw[4]), "r"(hw[5]), "r"(hw[6]), "r"(hw[7]));
        asm volatile("st.shared.v4.b32 [%0], {%1,%2,%3,%4};" :: "r"(rb + (((4 + half*2 + 0) ^ px) << 4)),
                     "r"(lw[0]), "r"(lw[1]), "r"(lw[2]), "r"(lw[3]));
        asm volatile("st.shared.v4.b32 [%0], {%1,%2,%3,%4};" :: "r"(rb + (((4 + half*2 + 1) ^ px) << 4)),
                     "r"(lw[4]), "r"(lw[5]), "r"(lw[6]), "r"(lw[7]));
    }
    __syncthreads();

    float4 acc[8];
    #pragma unroll
    for (int i = 0; i < 8; i++) acc[i] = make_float4(0,0,0,0);
    const int aRow = wid*16 + (lane & 15);
    const int aXor = aRow & 7, aHalf = lane >> 4;
    const int bRow8 = (lane >> 4)*8 + (lane & 7);
    const int bHalf = (lane >> 3) & 1, bx = lane & 7;
    #pragma unroll
    for (int ks = 0; ks < 2; ks++) {
        uint32_t ah[4], al[4];
        const uint32_t ab = sb + oA + aRow*128;
        ldsm_x4(ah, ab + (((2*ks + aHalf) ^ aXor) << 4));
        ldsm_x4(al, ab + (((4 + 2*ks + aHalf) ^ aXor) << 4));
        #pragma unroll
        for (int p = 0; p < 4; p++) {
            const uint32_t rbase = sb + oB + (p*16 + bRow8)*128;
            uint32_t bh[4];
            ldsm_x4(bh, rbase + (((2*ks + bHalf) ^ bx) << 4));
            mma16816(acc[2*p],   ah, bh);     mma16816(acc[2*p+1], ah, bh + 2);
            mma16816(acc[2*p],   al, bh);     mma16816(acc[2*p+1], al, bh + 2);
        }
    }

    __syncthreads();
    float* so = reinterpret_cast<float*>(smp);
    {
        const int row = wid*16 + (lane >> 2);
        const int col = 2*(lane & 3);
        #pragma unroll
        for (int nb = 0; nb < 8; nb++) {
            so[row*64 + nb*8 + col]       = acc[nb].x;
            so[row*64 + nb*8 + col + 1]   = acc[nb].y;
            so[(row+8)*64 + nb*8 + col]   = acc[nb].z;
            so[(row+8)*64 + nb*8 + col+1] = acc[nb].w;
        }
    }
    __syncthreads();
    for (int g = tid; g < 32*8; g += 256) {
        int pp_l = g >> 3, cg = g & 7;
        int pp = ppb + pp_l;
        if (pp >= NPX) continue;
        int co0 = cg*8;
        float v[8];
        #pragma unroll
        for (int j = 0; j < 8; j++) v[j] = -1e30f;
        #pragma unroll
        for (int q = 0; q < 4; q++) {
            const float* rp = &so[(4*pp_l + q)*64 + co0];
            #pragma unroll
            for (int j = 0; j < 8; j++) v[j] = fmaxf(v[j], rp[j]);
        }
        unsigned short hh[8], ll[8];
        #pragma unroll
        for (int j = 0; j < 8; j++) {
            float t = fmaxf(v[j] + bias[co0 + j], 0.f);
            f16 h = __float2half_rn(t);
            hh[j] = __half_as_ushort(h);
            ll[j] = __half_as_ushort(__float2half_rn(t - __half2float(h)));
        }
        size_t base = (((size_t)img*HPO + pp/WPO)*WPO + pp%WPO)*64 + co0;
        *reinterpret_cast<uint4*>(outh + base) =
            make_uint4(hh[0]|((uint32_t)hh[1]<<16), hh[2]|((uint32_t)hh[3]<<16),
                       hh[4]|((uint32_t)hh[5]<<16), hh[6]|((uint32_t)hh[7]<<16));
        *reinterpret_cast<uint4*>(outl + base) =
            make_uint4(ll[0]|((uint32_t)ll[1]<<16), ll[2]|((uint32_t)ll[3]<<16),
                       ll[4]|((uint32_t)ll[5]<<16), ll[6]|((uint32_t)ll[7]<<16));
    }
}

// ---------- HMMA conv, pixels-on-M (L2, L3): A = act hi/lo, B = weights single ----------
template<int COUT, int HIN, int WIN, int HPO, int WPO, int NROWS, int PW>
__global__ void __launch_bounds__(256, 2)
conv_mma_px(const f16* __restrict__ inh, const f16* __restrict__ inl,
            const f16* __restrict__ wgt, const float* __restrict__ bias,
            f16* __restrict__ outh, f16* __restrict__ outl)
{
    constexpr int NT = 256, MP = 32;
    constexpr int NB = COUT/8;
    constexpr int NPAIR = NB/2;
    constexpr int BANDPX = NROWS*PW;
    constexpr uint32_t BH = BANDPX*128;
    constexpr uint32_t CB = COUT*128;
    constexpr uint32_t oB = 2*BH;

    extern __shared__ char dsm[];
    char* smp = (char*)(((uintptr_t)dsm + 1023) & ~(uintptr_t)1023);
    const uint32_t sb = smem_u32(smp);
    const int tid = threadIdx.x, wid = tid >> 5, lane = tid & 31;
    const int img = blockIdx.z, ppb = blockIdx.x * MP;
    const int r0 = ppb / WPO;
    const int ystart = 2*r0 - 1;

    const f16* ih = inh + (size_t)img * HIN * WIN * 64;
    const f16* il = inl + (size_t)img * HIN * WIN * 64;

    for (int g = tid; g < BANDPX*8; g += NT) {
        int p = g >> 3, seg = g & 7;
        int row = p / PW, col = p % PW;
        int gy = ystart + row, gx = col - 1;
        bool ok = (gy >= 0 && gy < HIN && gx >= 0 && gx < WIN);
        size_t s = ok ? (((size_t)gy*WIN + gx)*64 + seg*8) : 0;
        uint32_t d = p*128 + ((seg ^ (p & 7)) << 4);
        cpa16(sb + d,      ih + s, ok ? 16 : 0);
        cpa16(sb + BH + d, il + s, ok ? 16 : 0);
    }
    for (int g = tid; g < COUT*8; g += NT) {
        int r = g >> 3, seg = g & 7;
        cpa16(sb + oB + r*128 + ((seg ^ (r & 7)) << 4), wgt + (size_t)r*64 + seg*8, 16);
    }
    CPA_COMMIT();

    float4 acc[NB];
    #pragma unroll
    for (int i = 0; i < NB; i++) acc[i] = make_float4(0,0,0,0);

    const int aRow = wid*16 + (lane & 15);
    const int appd = aRow >> 2, aq = aRow & 3;
    const int ay = 2*((ppb + appd)/WPO) + (aq >> 1);
    const int ax = 2*((ppb + appd)%WPO) + (aq & 1);
    const int p00 = (ay - 2*r0)*PW + ax;
    const int aHalf = lane >> 4;
    const int bRow8 = (lane >> 4)*8 + (lane & 7);
    const int bHalf = (lane >> 3) & 1, bx = lane & 7;

    for (int k = 0; k < 9; k++) {
        if (k > 0) {
            __syncthreads();
            for (int g = tid; g < COUT*8; g += NT) {
                int r = g >> 3, seg = g & 7;
                cpa16(sb + oB + r*128 + ((seg ^ (r & 7)) << 4),
                      wgt + ((size_t)k*COUT + r)*64 + seg*8, 16);
            }
            CPA_COMMIT();
        }
        CPA_WAIT0();
        __syncthreads();
        const int pA = p00 + (k/3)*PW + (k%3);
        const uint32_t aBaseH = sb + pA*128;
        const uint32_t aBaseL = sb + BH + pA*128;
        const int aXor = pA & 7;
        #pragma unroll
        for (int ks = 0; ks < 4; ks++) {
            uint32_t ah[4], al[4];
            const uint32_t ao = (uint32_t)(((2*ks + aHalf) ^ aXor) << 4);
            ldsm_x4(ah, aBaseH + ao);
            ldsm_x4(al, aBaseL + ao);
            #pragma unroll
            for (int p = 0; p < NPAIR; p++) {
                const uint32_t rbase = sb + oB + (p*16 + bRow8)*128 + (((2*ks + bHalf) ^ bx) << 4);
                uint32_t bh[4];
                ldsm_x4(bh, rbase);
                mma16816(acc[2*p],   ah, bh);     mma16816(acc[2*p+1], ah, bh + 2);
                mma16816(acc[2*p],   al, bh);     mma16816(acc[2*p+1], al, bh + 2);
            }
        }
    }

    __syncthreads();
    float* so = reinterpret_cast<float*>(smp);
    {
        const int row = wid*16 + (lane >> 2);
        const int col = 2*(lane & 3);
        #pragma unroll
        for (int nb = 0; nb < NB; nb++) {
            so[row*COUT + nb*8 + col]       = acc[nb].x;
            so[row*COUT + nb*8 + col + 1]   = acc[nb].y;
            so[(row+8)*COUT + nb*8 + col]   = acc[nb].z;
            so[(row+8)*COUT + nb*8 + col+1] = acc[nb].w;
        }
    }
    __syncthreads();
    for (int g = tid; g < MP*NB; g += NT) {
        int pp_l = g / NB, cg = g % NB;
        int pp = ppb + pp_l;
        if (pp >= HPO*WPO) continue;
        int co0 = cg*8;
        float v[8];
        #pragma unroll
        for (int j = 0; j < 8; j++) v[j] = -1e30f;
        #pragma unroll
        for (int q = 0; q < 4; q++) {
            const float* rp = &so[(4*pp_l + q)*COUT + co0];
            #pragma unroll
            for (int j = 0; j < 8; j++) v[j] = fmaxf(v[j], rp[j]);
        }
        unsigned short hh[8], ll[8];
        #pragma unroll
        for (int j = 0; j < 8; j++) {
            float t = fmaxf(v[j] + bias[co0 + j], 0.f);
            f16 h = __float2half_rn(t);
            hh[j] = __half_as_ushort(h);
            ll[j] = __half_as_ushort(__float2half_rn(t - __half2float(h)));
        }
        size_t base = (((size_t)img*HPO + pp/WPO)*WPO + pp%WPO)*COUT + co0;
        *reinterpret_cast<uint4*>(outh + base) =
            make_uint4(hh[0]|((uint32_t)hh[1]<<16), hh[2]|((uint32_t)hh[3]<<16),
                       hh[4]|((uint32_t)hh[5]<<16), hh[6]|((uint32_t)hh[7]<<16));
        *reinterpret_cast<uint4*>(outl + base) =
            make_uint4(ll[0]|((uint32_t)ll[1]<<16), ll[2]|((uint32_t)ll[3]<<16),
                       ll[4]|((uint32_t)ll[5]<<16), ll[6]|((uint32_t)ll[7]<<16));
    }
}

// ---------- HMMA conv, co-on-M (L4): A = weights single, B = pixels hi/lo ----------
__global__ void __launch_bounds__(256, 2)
conv_mma_co(const f16* __restrict__ inh, const f16* __restrict__ inl,
            const f16* __restrict__ wgt, const float* __restrict__ bias,
            float* __restrict__ outf)
{
    constexpr int NT = 256;
    constexpr uint32_t PXB = 144*256;
    constexpr uint32_t oPxL = PXB, oA = 2*PXB;

    extern __shared__ char dsm[];
    char* smp = (char*)(((uintptr_t)dsm + 1023) & ~(uintptr_t)1023);
    const uint32_t sb = smem_u32(smp);
    const int tid = threadIdx.x, wid = tid >> 5, lane = tid & 31;
    const int img = blockIdx.z, cob = blockIdx.y * 128;

    const f16* ih = inh + (size_t)img * 100 * 128;
    const f16* il = inl + (size_t)img * 100 * 128;

    for (int g = tid; g < 144*16; g += NT) {
        int p = g >> 4, seg = g & 15;
        int row = p / 12, col = p % 12;
        int gy = row - 1, gx = col - 1;
        bool ok = (gy >= 0 && gy < 10 && gx >= 0 && gx < 10);
        size_t s = ok ? ((size_t)(gy*10 + gx)*128 + seg*8) : 0;
        uint32_t d = p*256 + ((seg ^ (p & 7)) << 4);
        cpa16(sb + d,        ih + s, ok ? 16 : 0);
        cpa16(sb + oPxL + d, il + s, ok ? 16 : 0);
    }
    for (int g = tid; g < 1024; g += NT) {
        int m = g >> 3, seg = g & 7;
        cpa16(sb + oA + m*128 + ((seg ^ (m & 7)) << 4),
              wgt + ((size_t)cob + m)*64 + seg*8, 16);
    }
    CPA_COMMIT();

    float4 acc[13];
    #pragma unroll
    for (int i = 0; i < 13; i++) acc[i] = make_float4(0,0,0,0);

    const int aRow = wid*16 + (lane & 15);
    const int aXor = aRow & 7, aHalf = lane >> 4;
    const int bHalf = (lane >> 3) & 1;
    int pb0[7];
    #pragma unroll
    for (int p = 0; p < 7; p++) {
        int n = (p < 6) ? (p*16 + (lane >> 4)*8 + (lane & 7)) : (96 + (lane & 7));
        int pp = n >> 2, q = n & 3;
        if (pp < 25) {
            int y = 2*(pp/5) + (q >> 1);
            int x = 2*(pp%5) + (q & 1);
            pb0[p] = (y + 1)*12 + (x + 1);
        } else pb0[p] = 20;
    }

    for (int it = 0; it < 18; it++) {
        if (it > 0) {
            __syncthreads();
            int kn = it >> 1, cn = it & 1;
            for (int g = tid; g < 1024; g += NT) {
                int m = g >> 3, seg = g & 7;
                cpa16(sb + oA + m*128 + ((seg ^ (m & 7)) << 4),
                      wgt + ((size_t)(kn*2 + cn)*512 + cob + m)*64 + seg*8, 16);
            }
            CPA_COMMIT();
        }
        CPA_WAIT0();
        __syncthreads();
        const int k = it >> 1, cic = it & 1;
        const int dtap = (k/3 - 1)*12 + (k%3 - 1);
        const uint32_t aBase = sb + oA + aRow*128;
        #pragma unroll
        for (int ks = 0; ks < 4; ks++) {
            uint32_t ah[4];
            ldsm_x4(ah, aBase + (uint32_t)(((2*ks + aHalf) ^ aXor) << 4));
            #pragma unroll
            for (int p = 0; p < 6; p++) {
                const int pb = pb0[p] + dtap;
                const uint32_t bo = sb + pb*256 + ((((cic<<3) + 2*ks + bHalf) ^ (pb & 7)) << 4);
                uint32_t bh[4], bl[4];
                ldsm_x4(bh, bo);
                ldsm_x4(bl, bo + oPxL);
                mma16816(acc[2*p],   ah, bh);     mma16816(acc[2*p+1], ah, bh + 2);
                mma16816(acc[2*p],   ah, bl);     mma16816(acc[2*p+1], ah, bl + 2);
            }
            {
                const int pb = pb0[6] + dtap;
                const uint32_t bo = sb + pb*256 + ((((cic<<3) + 2*ks + bHalf) ^ (pb & 7)) << 4);
                uint32_t bh[2], bl[2];
                ldsm_x2(bh, bo);
                ldsm_x2(bl, bo + oPxL);
                mma16816(acc[12], ah, bh);
                mma16816(acc[12], ah, bl);
            }
        }
    }

    __syncthreads();
    float* so = reinterpret_cast<float*>(smp);
    {
        const int row = wid*16 + (lane >> 2);
        const int col = 2*(lane & 3);
        #pragma unroll
        for (int nb = 0; nb < 13; nb++) {
            so[row*104 + nb*8 + col]       = acc[nb].x;
            so[row*104 + nb*8 + col + 1]   = acc[nb].y;
            so[(row+8)*104 + nb*8 + col]   = acc[nb].z;
            so[(row+8)*104 + nb*8 + col+1] = acc[nb].w;
        }
    }
    __syncthreads();
    for (int g = tid; g < 3200; g += NT) {
        int co_l = g / 25, pp = g % 25;
        float4 q4 = *reinterpret_cast<float4*>(&so[co_l*104 + 4*pp]);
        float v = fmaxf(fmaxf(q4.x, q4.y), fmaxf(q4.z, q4.w));
        v = fmaxf(v + bias[cob + co_l], 0.f);
        outf[((size_t)img*512 + cob + co_l)*25 + pp] = v;
    }
}

// ---------- prototypes / head / scores ----------
__global__ void proto_kernel(const float* __restrict__ ytr) {
    const int bk = blockIdx.x, b = bk/5, k = bk - b*5, c = threadIdx.x;
    float ssum = 0.f, ysum = 0.f;
    for (int n = 0; n < 25; n++) {
        float y = ytr[(b*25 + n)*5 + k];
        ysum += y;
        if (y != 0.f) {
            const float* fp = &g_f4[((size_t)(b*25 + n)*512 + c)*25];
            float sp = 0.f;
            #pragma unroll
            for (int p = 0; p < 25; p++) sp += fp[p];
            ssum = fmaf(y, sp, ssum);
        }
    }
    float val = ssum / (ysum * 25.f);
    __shared__ float red[512];
    red[c] = val*val; __syncthreads();
    for (int o = 256; o > 0; o >>= 1) { if (c < o) red[c] += red[c+o]; __syncthreads(); }
    g_fa[(size_t)bk*512 + c] = val / fmaxf(sqrtf(red[0]), 1e-12f);
}
__global__ void predict_kernel(const float* __restrict__ wc, const float* __restrict__ bc,
                               float* __restrict__ out) {
    const int q = blockIdx.x, c = threadIdx.x;
    const float* fp = &g_f4[((size_t)(100 + q)*512 + c)*25];
    float s = 0.f;
    #pragma unroll
    for (int p = 0; p < 25; p++) s += fp[p];
    s /= 25.f;
    __shared__ float red[512], sf[512];
    red[c] = s*s; __syncthreads();
    for (int o = 256; o > 0; o >>= 1) { if (c < o) red[c] += red[c+o]; __syncthreads(); }
    sf[c] = s / fmaxf(sqrtf(red[0]), 1e-12f);
    __syncthreads();
    if (c < 64) {
        float a = bc[c];
        const float* wr = &wc[(size_t)c*512];
        #pragma unroll 8
        for (int d = 0; d < 512; d++) a = fmaf(sf[d], wr[d], a);
        out[(size_t)q*64 + c] = a;
    }
}
__global__ void score_kernel(float* __restrict__ out) {
    constexpr int CH = 128;
    __shared__ float sf[CH*25], sfa[5*129], snrm[25];
    const int q = blockIdx.x, b = q/75, tid = threadIdx.x;
    const float* fbase = &g_f4[(size_t)(100 + q)*512*25];
    float acc = 0.f;
    const int di = tid/25, dp = tid%25, pn = tid - 125;
    for (int cb = 0; cb < 4; cb++) {
        __syncthreads();
        for (int i = tid; i < CH*25; i += 256) sf[i] = fbase[cb*CH*25 + i];
        for (int i = tid; i < 5*CH; i += 256) {
            int ii = i/CH, cc = i - ii*CH;
            sfa[ii*129 + cc] = g_fa[((size_t)(b*5 + ii))*512 + cb*CH + cc];
        }
        __syncthreads();
        if (tid < 125) {
            #pragma unroll 4
            for (int c = 0; c < CH; c++) acc = fmaf(sf[c*25 + dp], sfa[di*129 + c], acc);
        } else if (tid < 150) {
            #pragma unroll 4
            for (int c = 0; c < CH; c++) { float v = sf[c*25 + pn]; acc = fmaf(v, v, acc); }
        }
    }
    if (tid >= 125 && tid < 150) snrm[pn] = fmaxf(sqrtf(acc), 1e-12f);
    __syncthreads();
    if (tid < 125) out[(size_t)q*125 + tid] = acc / snrm[dp];
}

// ---------- launch ----------
extern "C" void kernel_launch(void* const* d_in, const int* in_sizes, int n_in,
                              void* d_out, int out_size)
{
    const float* xtr = (const float*)d_in[0];
    const float* xte = (const float*)d_in[1];
    const float* ytr = (const float*)d_in[2];
    const float* w1 = (const float*)d_in[4];  const float* b1 = (const float*)d_in[5];
    const float* w2 = (const float*)d_in[6];  const float* b2 = (const float*)d_in[7];
    const float* w3 = (const float*)d_in[8];  const float* b3 = (const float*)d_in[9];
    const float* w4 = (const float*)d_in[10]; const float* b4 = (const float*)d_in[11];
    const float* wc = (const float*)d_in[12]; const float* bc = (const float*)d_in[13];
    float* out = (float*)d_out;

    float *f4;
    f16 *a1h,*a1l,*a2h,*a2l,*a3h,*a3l,*w1q,*w2p,*w3p,*w4p;
    cudaGetSymbolAddress((void**)&f4, g_f4);
    cudaGetSymbolAddress((void**)&w1q, g_w1q);
    cudaGetSymbolAddress((void**)&a1h, g_a1h); cudaGetSymbolAddress((void**)&a1l, g_a1l);
    cudaGetSymbolAddress((void**)&a2h, g_a2h); cudaGetSymbolAddress((void**)&a2l, g_a2l);
    cudaGetSymbolAddress((void**)&a3h, g_a3h); cudaGetSymbolAddress((void**)&a3l, g_a3l);
    cudaGetSymbolAddress((void**)&w2p, g_w2);
    cudaGetSymbolAddress((void**)&w3p, g_w3);
    cudaGetSymbolAddress((void**)&w4p, g_w4);

    repack_w1_kernel<<<8, 256>>>(w1, w1q);
    repack_f16_kernel<<<144, 256>>>(w2, w2p, 64, 64);
    repack_f16_kernel<<<288, 256>>>(w3, w3p, 64, 128);
    repack_f16_kernel<<<2304, 256>>>(w4, w4p, 128, 512);

    {   // L1 HMMA
        int sm = 33792;
        cudaFuncSetAttribute(conv1_mma, cudaFuncAttributeMaxDynamicSharedMemorySize, sm);
        conv1_mma<<<dim3(56, 1, 400), 256, sm>>>(xtr, xte, 100, w1q, b1, a1h, a1l);
    }
    {   // L2: 64->64, MP=32, band 8x44, single-buf B (8KB)
        auto kfn = conv_mma_px<64, 42, 42, 21, 21, 8, 44>;
        int sm = 1024 + 2*(8*44*128) + 64*128;
        cudaFuncSetAttribute(kfn, cudaFuncAttributeMaxDynamicSharedMemorySize, sm);
        kfn<<<dim3(14, 1, 400), 256, sm>>>(a1h, a1l, w2p, b2, a2h, a2l);
    }
    {   // L3: 64->128, MP=32, band 10x28, single-buf B (16KB)
        auto kfn = conv_mma_px<128, 21, 21, 10, 10, 10, 28>;
        int sm = 1024 + 2*(10*28*128) + 128*128;
        cudaFuncSetAttribute(kfn, cudaFuncAttributeMaxDynamicSharedMemorySize, sm);
        kfn<<<dim3(4, 1, 400), 256, sm>>>(a2h, a2l, w3p, b3, a3h, a3l);
    }
    {   // L4: 128->512, 12x12 band, single-buf A (16KB)
        int sm = 1024 + 2*(144*256) + 16384;
        cudaFuncSetAttribute(conv_mma_co, cudaFuncAttributeMaxDynamicSharedMemorySize, sm);
        conv_mma_co<<<dim3(1, 4, 400), 256, sm>>>(a3h, a3l, w4p, b4, f4);
    }

    proto_kernel<<<20, 512>>>(ytr);
    predict_kernel<<<300, 512>>>(wc, bc, out);
    score_kernel<<<300, 256>>>(out + 300*64);
}